// round 2
// baseline (speedup 1.0000x reference)
#include <cuda_runtime.h>
#include <math.h>
#include <stdint.h>

#define B_ 64
#define T_ 512
#define H_ 1024
#define C_ 21

// ---------------- GEMM: emissions = hs @ W + b ----------------
// Persistent grid (152 blocks = 1/SM), 8 warps/block.
// W kept in shared (pad 24 floats/row, float4-friendly, broadcast reads).
// Each group = 32 rows; lane = row; warp w covers H-range [w*128, w*128+128).
// Cross-warp partials combined through shared, coalesced stores.

#define GEMM_GRID 152
#define NW 8
#define WPAD 24
#define NGROUPS ((B_ * T_) / 32)   // 1024
#define H_PER_WARP (H_ / NW)       // 128

__global__ void __launch_bounds__(256, 1)
gemm_kernel(const float* __restrict__ hs, const float* __restrict__ W,
            const float* __restrict__ bias, float* __restrict__ out)
{
    extern __shared__ float smem[];
    float* sW    = smem;                         // 1024*24
    float* sTile = sW + H_ * WPAD;               // 8 * 32*33
    float* sRed  = sTile + NW * 32 * 33;         // 8 * 32*21

    // Load W into shared once (padded rows)
    for (int idx = threadIdx.x; idx < H_ * C_; idx += blockDim.x) {
        int h = idx / C_;
        int j = idx - h * C_;
        sW[h * WPAD + j] = W[idx];
    }
    __syncthreads();

    const int warp = threadIdx.x >> 5;
    const int lane = threadIdx.x & 31;
    float* myTile = sTile + warp * (32 * 33);
    const int h0w = warp * H_PER_WARP;

    for (int g = blockIdx.x; g < NGROUPS; g += gridDim.x) {
        const int row0 = g * 32;
        float acc[C_];
#pragma unroll
        for (int j = 0; j < C_; j++) acc[j] = 0.f;

        for (int c = 0; c < H_PER_WARP; c += 32) {
            const int hbase = h0w + c;
            // stage 32 rows x 32 h, coalesced
#pragma unroll 8
            for (int r = 0; r < 32; r++) {
                myTile[r * 33 + lane] = hs[(size_t)(row0 + r) * H_ + hbase + lane];
            }
            __syncwarp();
#pragma unroll 8
            for (int hh = 0; hh < 32; hh++) {
                const float x = myTile[lane * 33 + hh];
                const float* wr = sW + (hbase + hh) * WPAD;
                const float4 wa = *(const float4*)(wr + 0);
                const float4 wb = *(const float4*)(wr + 4);
                const float4 wc = *(const float4*)(wr + 8);
                const float4 wd = *(const float4*)(wr + 12);
                const float4 we = *(const float4*)(wr + 16);
                const float  wf = wr[20];
                acc[0]  = fmaf(x, wa.x, acc[0]);
                acc[1]  = fmaf(x, wa.y, acc[1]);
                acc[2]  = fmaf(x, wa.z, acc[2]);
                acc[3]  = fmaf(x, wa.w, acc[3]);
                acc[4]  = fmaf(x, wb.x, acc[4]);
                acc[5]  = fmaf(x, wb.y, acc[5]);
                acc[6]  = fmaf(x, wb.z, acc[6]);
                acc[7]  = fmaf(x, wb.w, acc[7]);
                acc[8]  = fmaf(x, wc.x, acc[8]);
                acc[9]  = fmaf(x, wc.y, acc[9]);
                acc[10] = fmaf(x, wc.z, acc[10]);
                acc[11] = fmaf(x, wc.w, acc[11]);
                acc[12] = fmaf(x, wd.x, acc[12]);
                acc[13] = fmaf(x, wd.y, acc[13]);
                acc[14] = fmaf(x, wd.z, acc[14]);
                acc[15] = fmaf(x, wd.w, acc[15]);
                acc[16] = fmaf(x, we.x, acc[16]);
                acc[17] = fmaf(x, we.y, acc[17]);
                acc[18] = fmaf(x, we.z, acc[18]);
                acc[19] = fmaf(x, we.w, acc[19]);
                acc[20] = fmaf(x, wf,   acc[20]);
            }
            __syncwarp();
        }

        // write per-warp partials (lane stride 21 words -> conflict-free)
        float* myRed = sRed + warp * (32 * C_);
#pragma unroll
        for (int j = 0; j < C_; j++) myRed[lane * C_ + j] = acc[j];
        __syncthreads();

        // combine across 8 warps + bias, coalesced store
        for (int idx = threadIdx.x; idx < 32 * C_; idx += blockDim.x) {
            float s = 0.f;
#pragma unroll
            for (int w2 = 0; w2 < NW; w2++) s += sRed[w2 * (32 * C_) + idx];
            int j = idx % C_;
            out[(size_t)row0 * C_ + idx] = s + bias[j];
        }
        __syncthreads();
    }
}

// ---------------- CRF: per-sequence forward in exp space ----------------

__device__ float g_llh[B_];

__global__ void __launch_bounds__(32, 1)
crf_kernel(const float* __restrict__ em_all, const float* __restrict__ trans,
           const float* __restrict__ startT, const float* __restrict__ endT,
           const int* __restrict__ att, const int* __restrict__ labels)
{
    const int b = blockIdx.x;
    const int lane = threadIdx.x;
    const float* em = em_all + (size_t)b * T_ * C_;
    const int* tag = labels + b * T_;
    const int* mrow = att + b * T_;
    const unsigned FULL = 0xffffffffu;

    // sequence length L (mask is a true prefix; position 0 forced true)
    int cnt = 0;
    for (int t = lane; t < T_; t += 32) {
        bool mk = (t == 0) ? true : (mrow[t] != 0 && tag[t] != -100);
        cnt += mk ? 1 : 0;
    }
#pragma unroll
    for (int o = 16; o; o >>= 1) cnt += __shfl_xor_sync(FULL, cnt, o);
    const int L = cnt;

    // numerator (parallel over t)
    float part = 0.f;
    for (int t = 1 + lane; t < L; t += 32) {
        part += trans[tag[t - 1] * C_ + tag[t]] + em[t * C_ + tag[t]];
    }
#pragma unroll
    for (int o = 16; o; o >>= 1) part += __shfl_xor_sync(FULL, part, o);
    float num = part + startT[tag[0]] + em[tag[0]] + endT[tag[L - 1]];

    // forward recursion: v_t = exp(em_t) .* (E^T v_{t-1}),  E = exp(trans)
    __shared__ __align__(16) float sV[2][24];
    const bool act = (lane < C_);
    const int j = act ? lane : 0;

    float Ej[C_];
#pragma unroll
    for (int i = 0; i < C_; i++) Ej[i] = __expf(trans[i * C_ + j]);
    const float eend = __expf(endT[j]);

    float a0 = startT[j] + em[j];
    float m0 = __shfl_sync(FULL, a0, 0);
    float acc = m0;
    float v0 = act ? __expf(a0 - m0) : 0.f;
    if (lane < 24) sV[0][lane] = act ? v0 : 0.f;
    __syncwarp();

    float emNext = em[C_ + j];   // t = 1 (T_ >= 2)
    int buf = 0;
    for (int t = 1; t < L; t++) {
        const float4 p0 = *(const float4*)&sV[buf][0];
        const float4 p1 = *(const float4*)&sV[buf][4];
        const float4 p2 = *(const float4*)&sV[buf][8];
        const float4 p3 = *(const float4*)&sV[buf][12];
        const float4 p4 = *(const float4*)&sV[buf][16];
        const float  p5 = sV[buf][20];

        float sA = 0.f, sB = 0.f, sC = 0.f;
        sA = fmaf(Ej[0],  p0.x, sA); sB = fmaf(Ej[1],  p0.y, sB); sC = fmaf(Ej[2],  p0.z, sC);
        sA = fmaf(Ej[3],  p0.w, sA); sB = fmaf(Ej[4],  p1.x, sB); sC = fmaf(Ej[5],  p1.y, sC);
        sA = fmaf(Ej[6],  p1.z, sA); sB = fmaf(Ej[7],  p1.w, sB); sC = fmaf(Ej[8],  p2.x, sC);
        sA = fmaf(Ej[9],  p2.y, sA); sB = fmaf(Ej[10], p2.z, sB); sC = fmaf(Ej[11], p2.w, sC);
        sA = fmaf(Ej[12], p3.x, sA); sB = fmaf(Ej[13], p3.y, sB); sC = fmaf(Ej[14], p3.z, sC);
        sA = fmaf(Ej[15], p3.w, sA); sB = fmaf(Ej[16], p4.x, sB); sC = fmaf(Ej[17], p4.y, sC);
        sA = fmaf(Ej[18], p4.z, sA); sB = fmaf(Ej[19], p4.w, sB); sC = fmaf(Ej[20], p5,   sC);
        float s = (sA + sB) + sC;

        float eet = __expf(emNext);
        if (t + 1 < T_) emNext = em[(t + 1) * C_ + j];
        float u = s * eet;

        if ((t & 3) == 0 || t == L - 1) {       // periodic renormalization
            float c = __shfl_sync(FULL, u, 0);
            acc += __logf(c);
            u = u * __fdividef(1.f, c);
        }
        buf ^= 1;
        if (act) sV[buf][lane] = u;
        __syncwarp();
    }

    // logZ = acc + log( sum_j v_j * exp(end_j) )
    float vf = act ? sV[buf][lane] : 0.f;
    float z = vf * eend;
#pragma unroll
    for (int o = 16; o; o >>= 1) z += __shfl_xor_sync(FULL, z, o);
    float logZ = acc + __logf(z);

    if (lane == 0) g_llh[b] = num - logZ;
}

__global__ void reduce_kernel(float* __restrict__ out_loss)
{
    const int lane = threadIdx.x;   // 64 threads
    __shared__ float sp[2];
    float v = g_llh[lane];
#pragma unroll
    for (int o = 16; o; o >>= 1) v += __shfl_xor_sync(0xffffffffu, v, o);
    if ((lane & 31) == 0) sp[lane >> 5] = v;
    __syncthreads();
    if (lane == 0) out_loss[0] = -(sp[0] + sp[1]) / (float)B_;
}

// ---------------- launch ----------------

extern "C" void kernel_launch(void* const* d_in, const int* in_sizes, int n_in,
                              void* d_out, int out_size)
{
    const float* hs     = (const float*)d_in[0];
    const float* W      = (const float*)d_in[1];
    const float* bias   = (const float*)d_in[2];
    const float* trans  = (const float*)d_in[3];
    const float* startT = (const float*)d_in[4];
    const float* endT   = (const float*)d_in[5];
    const int*   att    = (const int*)d_in[6];
    const int*   labels = (const int*)d_in[7];
    float* out = (float*)d_out;

    const size_t smem = (size_t)(H_ * WPAD + NW * 32 * 33 + NW * 32 * C_) * sizeof(float);
    cudaFuncSetAttribute(gemm_kernel, cudaFuncAttributeMaxDynamicSharedMemorySize, (int)smem);

    gemm_kernel<<<GEMM_GRID, 256, smem>>>(hs, W, bias, out);
    crf_kernel<<<B_, 32>>>(out, trans, startT, endT, att, labels);
    reduce_kernel<<<1, 64>>>(out + (out_size - 1));
}

// round 3
// speedup vs baseline: 1.4346x; 1.4346x over previous
#include <cuda_runtime.h>
#include <math.h>
#include <stdint.h>

#define B_ 64
#define T_ 512
#define H_ 1024
#define C_ 21

// ================= GEMM: emissions = hs @ W + b =================
// 152 persistent blocks (1/SM), 16 warps (512 thr).
// W in shared, rows padded to 24 floats (96B, 16B-aligned -> LDS.128).
// Warp w covers H slice [w*64, w*64+64) in two 32-wide chunks.
// f32x2 packed FMA: 10 packed + 1 scalar accumulator per row.
// Per-warp reduction buffer aliases the per-warp staging tile.

#define GEMM_GRID 152
#define NW 16
#define WPAD 24
#define NGROUPS ((B_ * T_) / 32)   // 1024
#define H_PER_WARP (H_ / NW)       // 64
#define TILE_WORDS (32 * 33)       // per-warp staging tile (and red buffer)

__device__ __forceinline__ unsigned long long pk2(float lo, float hi) {
    unsigned long long r;
    asm("mov.b64 %0, {%1, %2};" : "=l"(r) : "f"(lo), "f"(hi));
    return r;
}
__device__ __forceinline__ void upk2(unsigned long long v, float& lo, float& hi) {
    asm("mov.b64 {%0, %1}, %2;" : "=f"(lo), "=f"(hi) : "l"(v));
}
__device__ __forceinline__ unsigned long long fma2(unsigned long long a,
                                                   unsigned long long b,
                                                   unsigned long long c) {
    unsigned long long d;
    asm("fma.rn.f32x2 %0, %1, %2, %3;" : "=l"(d) : "l"(a), "l"(b), "l"(c));
    return d;
}

__global__ void __launch_bounds__(512, 1)
gemm_kernel(const float* __restrict__ hs, const float* __restrict__ W,
            const float* __restrict__ bias, float* __restrict__ out)
{
    extern __shared__ float smem[];
    float* sW    = smem;                 // 1024*24 = 24576 floats
    float* sTile = sW + H_ * WPAD;       // 16 * 32*33 = 16896 floats (also red)

    // Load W into shared once (padded rows)
    for (int idx = threadIdx.x; idx < H_ * C_; idx += blockDim.x) {
        int h = idx / C_;
        int j = idx - h * C_;
        sW[h * WPAD + j] = W[idx];
    }
    __syncthreads();

    const int warp = threadIdx.x >> 5;
    const int lane = threadIdx.x & 31;
    float* myTile = sTile + warp * TILE_WORDS;
    const int h0w = warp * H_PER_WARP;

    for (int g = blockIdx.x; g < NGROUPS; g += gridDim.x) {
        const int row0 = g * 32;
        unsigned long long acc2[10];
        float accS = 0.f;
#pragma unroll
        for (int k = 0; k < 10; k++) acc2[k] = 0ull;

#pragma unroll
        for (int c = 0; c < H_PER_WARP; c += 32) {
            const int hbase = h0w + c;
            // stage 32 rows x 32 h (coalesced LDG)
#pragma unroll 8
            for (int r = 0; r < 32; r++) {
                myTile[r * 33 + lane] = hs[(size_t)(row0 + r) * H_ + hbase + lane];
            }
            __syncwarp();
#pragma unroll 4
            for (int hh = 0; hh < 32; hh++) {
                const float x = myTile[lane * 33 + hh];
                const unsigned long long xx = pk2(x, x);
                const float* wr = sW + (hbase + hh) * WPAD;
                const ulonglong2* wp = (const ulonglong2*)wr;   // 16B aligned
                const ulonglong2 q0 = wp[0];
                const ulonglong2 q1 = wp[1];
                const ulonglong2 q2 = wp[2];
                const ulonglong2 q3 = wp[3];
                const ulonglong2 q4 = wp[4];
                const float wf = wr[20];
                acc2[0] = fma2(xx, q0.x, acc2[0]);
                acc2[1] = fma2(xx, q0.y, acc2[1]);
                acc2[2] = fma2(xx, q1.x, acc2[2]);
                acc2[3] = fma2(xx, q1.y, acc2[3]);
                acc2[4] = fma2(xx, q2.x, acc2[4]);
                acc2[5] = fma2(xx, q2.y, acc2[5]);
                acc2[6] = fma2(xx, q3.x, acc2[6]);
                acc2[7] = fma2(xx, q3.y, acc2[7]);
                acc2[8] = fma2(xx, q4.x, acc2[8]);
                acc2[9] = fma2(xx, q4.y, acc2[9]);
                accS    = fmaf(x, wf, accS);
            }
            __syncwarp();
        }

        // write per-warp partials into own tile area (lane stride 21: conflict-free)
        {
            float* myRed = myTile;
#pragma unroll
            for (int k = 0; k < 10; k++) {
                float lo, hi;
                upk2(acc2[k], lo, hi);
                myRed[lane * C_ + 2 * k]     = lo;
                myRed[lane * C_ + 2 * k + 1] = hi;
            }
            myRed[lane * C_ + 20] = accS;
        }
        __syncthreads();

        // combine across 16 warps + bias, coalesced store
        for (int idx = threadIdx.x; idx < 32 * C_; idx += blockDim.x) {
            float s = 0.f;
#pragma unroll
            for (int w2 = 0; w2 < NW; w2++) s += sTile[w2 * TILE_WORDS + idx];
            int j = idx % C_;
            out[(size_t)row0 * C_ + idx] = s + bias[j];
        }
        __syncthreads();
    }
}

// ============ CRF: per-sequence forward in exp space ============
// One block per sequence, 128 threads. All warps bulk-stage
// exp(emissions) into shared (removes global-load latency from the
// serial chain). Warp 0 then runs the recursion; warp 1 the numerator.

__device__ float g_llh[B_];

__global__ void __launch_bounds__(128, 1)
crf_kernel(const float* __restrict__ em_all, const float* __restrict__ trans,
           const float* __restrict__ startT, const float* __restrict__ endT,
           const int* __restrict__ att, const int* __restrict__ labels)
{
    __shared__ __align__(16) float sEexp[T_ * C_];   // 43008 B
    __shared__ __align__(16) float sV[2][24];
    __shared__ float sNum;

    const int b = blockIdx.x;
    const int tid = threadIdx.x;
    const int warp = tid >> 5;
    const int lane = tid & 31;
    const float* em = em_all + (size_t)b * T_ * C_;
    const int* tag = labels + b * T_;
    const int* mrow = att + b * T_;
    const unsigned FULL = 0xffffffffu;

    // Bulk-stage exp(em) for all T (float4, coalesced; MUFU off the chain)
    {
        const float4* em4 = (const float4*)em;          // base 16B aligned
        float4* se4 = (float4*)sEexp;
        const int n4 = (T_ * C_) / 4;                   // 2688
        for (int i = tid; i < n4; i += 128) {
            float4 v = em4[i];
            v.x = __expf(v.x); v.y = __expf(v.y);
            v.z = __expf(v.z); v.w = __expf(v.w);
            se4[i] = v;
        }
    }
    __syncthreads();

    // sequence length L (mask is a true prefix) — warps 0 and 1 independently
    int L = 0;
    if (warp < 2) {
        int cnt = 0;
        for (int t = lane; t < T_; t += 32) {
            bool mk = (t == 0) ? true : (mrow[t] != 0 && tag[t] != -100);
            cnt += mk ? 1 : 0;
        }
#pragma unroll
        for (int o = 16; o; o >>= 1) cnt += __shfl_xor_sync(FULL, cnt, o);
        L = cnt;
    }

    if (warp == 1) {
        // numerator (parallel over t)
        float part = 0.f;
        for (int t = 1 + lane; t < L; t += 32) {
            part += trans[tag[t - 1] * C_ + tag[t]] + em[t * C_ + tag[t]];
        }
#pragma unroll
        for (int o = 16; o; o >>= 1) part += __shfl_xor_sync(FULL, part, o);
        if (lane == 0)
            sNum = part + startT[tag[0]] + em[tag[0]] + endT[tag[L - 1]];
    }

    float logZ = 0.f;
    if (warp == 0) {
        const bool act = (lane < C_);
        const int j = act ? lane : 0;

        float Ej[C_];
#pragma unroll
        for (int i = 0; i < C_; i++) Ej[i] = __expf(trans[i * C_ + j]);
        const float eend = __expf(endT[j]);

        // w_j = exp(startT_j) * exp(em0_j); v0 = w_j / w_0; acc = log w_0
        float w = __expf(startT[j]) * sEexp[j];
        float w0 = __shfl_sync(FULL, w, 0);
        float acc = __logf(w0);
        float rw0 = __fdividef(1.f, w0);
        if (lane < 24) sV[0][lane] = act ? (w * rw0) : 0.f;
        __syncwarp();

        int buf = 0;
        for (int t = 1; t < L; t++) {
            const float4 p0 = *(const float4*)&sV[buf][0];
            const float4 p1 = *(const float4*)&sV[buf][4];
            const float4 p2 = *(const float4*)&sV[buf][8];
            const float4 p3 = *(const float4*)&sV[buf][12];
            const float4 p4 = *(const float4*)&sV[buf][16];
            const float  p5 = sV[buf][20];
            const float eet = sEexp[t * C_ + j];

            // 7 independent chains, depth 3
            float s0 = Ej[0] * p0.x, s1 = Ej[1] * p0.y, s2 = Ej[2] * p0.z;
            float s3 = Ej[3] * p0.w, s4 = Ej[4] * p1.x, s5 = Ej[5] * p1.y;
            float s6 = Ej[6] * p1.z;
            s0 = fmaf(Ej[7],  p1.w, s0); s1 = fmaf(Ej[8],  p2.x, s1);
            s2 = fmaf(Ej[9],  p2.y, s2); s3 = fmaf(Ej[10], p2.z, s3);
            s4 = fmaf(Ej[11], p2.w, s4); s5 = fmaf(Ej[12], p3.x, s5);
            s6 = fmaf(Ej[13], p3.y, s6);
            s0 = fmaf(Ej[14], p3.z, s0); s1 = fmaf(Ej[15], p3.w, s1);
            s2 = fmaf(Ej[16], p4.x, s2); s3 = fmaf(Ej[17], p4.y, s3);
            s4 = fmaf(Ej[18], p4.z, s4); s5 = fmaf(Ej[19], p4.w, s5);
            s6 = fmaf(Ej[20], p5,   s6);
            float s = ((s0 + s1) + (s2 + s3)) + ((s4 + s5) + s6);

            float u = s * eet;

            if ((t & 7) == 0) {                 // renorm every 8 steps
                float cnorm = __shfl_sync(FULL, u, 0);
                acc += __logf(cnorm);
                u = u * __fdividef(1.f, cnorm);
            }
            buf ^= 1;
            if (act) sV[buf][lane] = u;
            __syncwarp();
        }

        // logZ = acc + log( sum_j v_j * exp(end_j) )
        float vf = act ? sV[buf][lane] : 0.f;
        float z = vf * eend;
#pragma unroll
        for (int o = 16; o; o >>= 1) z += __shfl_xor_sync(FULL, z, o);
        logZ = acc + __logf(z);
    }

    __syncthreads();
    if (tid == 0) g_llh[b] = sNum - logZ;
}

__global__ void reduce_kernel(float* __restrict__ out_loss)
{
    const int lane = threadIdx.x;   // 64 threads
    __shared__ float sp[2];
    float v = g_llh[lane];
#pragma unroll
    for (int o = 16; o; o >>= 1) v += __shfl_xor_sync(0xffffffffu, v, o);
    if ((lane & 31) == 0) sp[lane >> 5] = v;
    __syncthreads();
    if (lane == 0) out_loss[0] = -(sp[0] + sp[1]) / (float)B_;
}

// ---------------- launch ----------------

extern "C" void kernel_launch(void* const* d_in, const int* in_sizes, int n_in,
                              void* d_out, int out_size)
{
    const float* hs     = (const float*)d_in[0];
    const float* W      = (const float*)d_in[1];
    const float* bias   = (const float*)d_in[2];
    const float* trans  = (const float*)d_in[3];
    const float* startT = (const float*)d_in[4];
    const float* endT   = (const float*)d_in[5];
    const int*   att    = (const int*)d_in[6];
    const int*   labels = (const int*)d_in[7];
    float* out = (float*)d_out;

    const size_t smem = (size_t)(H_ * WPAD + NW * TILE_WORDS) * sizeof(float);
    cudaFuncSetAttribute(gemm_kernel, cudaFuncAttributeMaxDynamicSharedMemorySize, (int)smem);

    gemm_kernel<<<GEMM_GRID, 512, smem>>>(hs, W, bias, out);
    crf_kernel<<<B_, 128>>>(out, trans, startT, endT, att, labels);
    reduce_kernel<<<1, 64>>>(out + (out_size - 1));
}